// round 5
// baseline (speedup 1.0000x reference)
#include <cuda_runtime.h>
#include <math.h>

#define TPB   768
#define BM    4
#define S_LEN 128
#define B_TOT 512
#define H     192
#define VOC   256
#define PP    64
#define PHH   16

// output buffer offsets (floats), concatenated in reference-return order
#define OFF_LOGITS 0
#define OFF_HIDDEN (512*128*256)
#define OFF_PW     (OFF_HIDDEN + 512*128*192)
#define OFF_PHW    (OFF_PW     + 512*128*64)
#define OFF_GATE   (OFF_PHW    + 512*128*16)

typedef unsigned long long u64t;

__device__ __forceinline__ u64t ffma2(u64t a, u64t b, u64t c) {
    u64t d;
    asm("fma.rn.f32x2 %0, %1, %2, %3;" : "=l"(d) : "l"(a), "l"(b), "l"(c));
    return d;
}
__device__ __forceinline__ u64t packdup(float w) {
    u64t d;
    asm("mov.b64 %0, {%1, %1};" : "=l"(d) : "f"(w));
    return d;
}

__device__ __forceinline__ float geluf(float x) {
    return 0.5f * x * (1.0f + erff(x * 0.7071067811865475f));
}

struct __align__(16) Smem {
    float xbuf[576 * BM];       // row-interleaved GEMM input: x[k*4 + r]
    float red [12288];          // [seg][n][r] partial scratch: NSEG*N*BM == 12288 all shapes
    float tok [BM * H];
    float prev[BM * H];
    float patch[BM * H];
    float sec [BM * H];
    float phs [BM * H];
    float succ[BM * H];
    float hbuf[BM * H];         // normal-format (gate1 out)
    float hbufri[H * BM];       // row-interleaved (bind1/succ1 out)
    float z64 [BM * PP];
    float z64ri[PP * BM];
    float z16 [BM * PHH];
    float z16ri[PHH * BM];
    float gate[BM];
    int   ids [BM];
};

// C[BM x N] = act( X[BM x K] @ W[K x N] + bias )
// X row-interleaved: entry k is 4 floats {x_r0..x_r3} at xri[k*4].
// thread -> (col group c4 = t % (N/4) owning 4 cols, kseg = t / (N/4)).
// ACT: 0 none, 1 gelu(exact), 2 tanh. OUTRI: write outs row-interleaved [n*4+r].
template<int K, int N, int ACT, bool HASB, bool OUTRI>
__device__ __forceinline__ void gemm(const float* __restrict__ xri,
                                     const float* __restrict__ W,
                                     const float* __restrict__ bias,
                                     float* __restrict__ red,
                                     float* __restrict__ outs,
                                     float* __restrict__ outg, int g_rstride)
{
    constexpr int NC4  = N / 4;
    constexpr int NSEG = TPB / NC4;
    constexpr int KS   = K / NSEG;
    static_assert(NC4 * NSEG == TPB, "thread mapping must be exact");
    static_assert(KS * NSEG == K,    "k split must be exact");

    const int t   = threadIdx.x;
    const int c4  = t % NC4;
    const int seg = t / NC4;
    const float4*     __restrict__ Wv = reinterpret_cast<const float4*>(W);
    const ulonglong2* __restrict__ Xv = reinterpret_cast<const ulonglong2*>(xri);

    // acc01[c] = {C_r0, C_r1} for col c4*4+c ; acc23[c] = {C_r2, C_r3}
    u64t acc01[4], acc23[4];
#pragma unroll
    for (int c = 0; c < 4; c++) { acc01[c] = 0ull; acc23[c] = 0ull; }

    const int k0 = seg * KS;
#pragma unroll 4
    for (int kk = 0; kk < KS; kk++) {
        const int k = k0 + kk;
        ulonglong2 xp = Xv[k];                 // {x_r0,x_r1},{x_r2,x_r3}
        float4 w = __ldg(&Wv[k * NC4 + c4]);
        u64t w0 = packdup(w.x), w1 = packdup(w.y), w2 = packdup(w.z), w3 = packdup(w.w);
        acc01[0] = ffma2(xp.x, w0, acc01[0]);
        acc23[0] = ffma2(xp.y, w0, acc23[0]);
        acc01[1] = ffma2(xp.x, w1, acc01[1]);
        acc23[1] = ffma2(xp.y, w1, acc23[1]);
        acc01[2] = ffma2(xp.x, w2, acc01[2]);
        acc23[2] = ffma2(xp.y, w2, acc23[2]);
        acc01[3] = ffma2(xp.x, w3, acc01[3]);
        acc23[3] = ffma2(xp.y, w3, acc23[3]);
    }

    // red[seg][n][r]: STS.128 per col = {C_r0,C_r1,C_r2,C_r3}
    ulonglong2* redv = reinterpret_cast<ulonglong2*>(red);
#pragma unroll
    for (int c = 0; c < 4; c++) {
        const int n = c4 * 4 + c;
        ulonglong2 st; st.x = acc01[c]; st.y = acc23[c];
        redv[seg * N + n] = st;
    }
    __syncthreads();

    for (int i = t; i < BM * N; i += TPB) {
        const int n = i >> 2;
        const int r = i & 3;
        float v = 0.f;
#pragma unroll
        for (int g = 0; g < NSEG; g++) v += red[(g * N + n) * BM + r];
        if (HASB) v += __ldg(&bias[n]);
        if (ACT == 1) v = geluf(v);
        if (ACT == 2) v = tanhf(v);
        if (outs) {
            if (OUTRI) outs[i] = v;            // i == n*4 + r
            else       outs[r * N + n] = v;
        }
        if (outg) outg[r * g_rstride + n] = v;
    }
    __syncthreads();
}

// warp-per-row softmax over N (<= 64): reads z (normal), writes zri (row-interleaved) + global
template<int N>
__device__ __forceinline__ void softmax_rows(const float* __restrict__ z,
                                             float* __restrict__ zri,
                                             float* __restrict__ outg, int g_rstride)
{
    const int w = threadIdx.x >> 5, lane = threadIdx.x & 31;
    if (w < BM) {
        const float* row = z + w * N;
        constexpr int PER = (N + 31) / 32;
        float m = -3.0e38f;
#pragma unroll
        for (int i = 0; i < PER; i++) {
            int n = lane + 32 * i;
            if (n < N) m = fmaxf(m, row[n]);
        }
#pragma unroll
        for (int o = 16; o; o >>= 1) m = fmaxf(m, __shfl_xor_sync(0xffffffffu, m, o));
        float ev[PER];
        float sum = 0.f;
#pragma unroll
        for (int i = 0; i < PER; i++) {
            int n = lane + 32 * i;
            if (n < N) { ev[i] = expf(row[n] - m); sum += ev[i]; }
        }
#pragma unroll
        for (int o = 16; o; o >>= 1) sum += __shfl_xor_sync(0xffffffffu, sum, o);
        const float inv = 1.f / sum;
#pragma unroll
        for (int i = 0; i < PER; i++) {
            int n = lane + 32 * i;
            if (n < N) {
                float v = ev[i] * inv;
                zri[n * BM + w] = v;
                outg[w * g_rstride + n] = v;
            }
        }
    }
}

__global__ void __launch_bounds__(TPB, 1)
spike_kernel(const int* __restrict__ ids_g,      const float* __restrict__ emb,
             const float* __restrict__ sel_W,    const float* __restrict__ sel_b,
             const float* __restrict__ patch_values,
             const float* __restrict__ bind_W1,  const float* __restrict__ bind_b1,
             const float* __restrict__ bind_W2,  const float* __restrict__ bind_b2,
             const float* __restrict__ phase_embed,
             const float* __restrict__ router_W, const float* __restrict__ router_b,
             const float* __restrict__ succ_W1,  const float* __restrict__ succ_b1,
             const float* __restrict__ succ_W2,  const float* __restrict__ succ_b2,
             const float* __restrict__ gate_W1,  const float* __restrict__ gate_b1,
             const float* __restrict__ gate_W2,  const float* __restrict__ gate_b2,
             const float* __restrict__ ln_g,     const float* __restrict__ ln_b,
             const float* __restrict__ dec_W,
             float* __restrict__ out)
{
    __shared__ Smem sm;
    const int t  = threadIdx.x;
    const int b0 = blockIdx.x * BM;

    float* out_logits = out + OFF_LOGITS;
    float* out_hidden = out + OFF_HIDDEN;
    float* out_pw     = out + OFF_PW;
    float* out_phw    = out + OFF_PHW;
    float* out_gate   = out + OFF_GATE;

    for (int i = t; i < BM * H; i += TPB) sm.prev[i] = 0.f;
    __syncthreads();

    for (int s = 0; s < S_LEN; s++) {
        if (t < BM) sm.ids[t] = ids_g[(b0 + t) * S_LEN + s];
        __syncthreads();

        // tok gather + build x1 = RI[tok, prev] (K=384)
        for (int i = t; i < BM * 384; i += TPB) {
            const int k = i >> 2, r = i & 3;
            float v;
            if (k < H) { v = __ldg(&emb[sm.ids[r] * H + k]); sm.tok[r * H + k] = v; }
            else       { v = sm.prev[r * H + (k - H)]; }
            sm.xbuf[i] = v;
        }
        __syncthreads();

        // patch selector: softmax(x1 @ sel_W + b) @ patch_values
        gemm<384, PP, 0, true, false>(sm.xbuf, sel_W, sel_b, sm.red, sm.z64, nullptr, 0);
        softmax_rows<PP>(sm.z64, sm.z64ri, out_pw + (b0 * S_LEN + s) * PP, S_LEN * PP);
        __syncthreads();
        gemm<PP, H, 0, false, false>(sm.z64ri, patch_values, nullptr, sm.red, sm.patch, nullptr, 0);

        // section binder: tanh(gelu(RI[tok,patch,prev] @ W1 + b1) @ W2 + b2)
        for (int i = t; i < BM * 576; i += TPB) {
            const int k = i >> 2, r = i & 3;
            float v = (k < H) ? sm.tok[r * H + k]
                    : (k < 2 * H) ? sm.patch[r * H + (k - H)]
                                  : sm.prev[r * H + (k - 2 * H)];
            sm.xbuf[i] = v;
        }
        __syncthreads();
        gemm<576, H, 1, true, true >(sm.xbuf,   bind_W1, bind_b1, sm.red, sm.hbufri, nullptr, 0);
        gemm<H,   H, 2, true, false>(sm.hbufri, bind_W2, bind_b2, sm.red, sm.sec,    nullptr, 0);

        // phase routing: softmax(RI[sec,prev] @ router_W + b) @ phase_embed
        for (int i = t; i < BM * 384; i += TPB) {
            const int k = i >> 2, r = i & 3;
            sm.xbuf[i] = (k < H) ? sm.sec[r * H + k] : sm.prev[r * H + (k - H)];
        }
        __syncthreads();
        gemm<384, PHH, 0, true, false>(sm.xbuf, router_W, router_b, sm.red, sm.z16, nullptr, 0);
        softmax_rows<PHH>(sm.z16, sm.z16ri, out_phw + (b0 * S_LEN + s) * PHH, S_LEN * PHH);
        __syncthreads();
        gemm<PHH, H, 0, false, false>(sm.z16ri, phase_embed, nullptr, sm.red, sm.phs, nullptr, 0);

        // successor: tanh(gelu(RI[sec,patch,phs] @ W1 + b1) @ W2 + b2)
        for (int i = t; i < BM * 576; i += TPB) {
            const int k = i >> 2, r = i & 3;
            float v = (k < H) ? sm.sec[r * H + k]
                    : (k < 2 * H) ? sm.patch[r * H + (k - H)]
                                  : sm.phs[r * H + (k - 2 * H)];
            sm.xbuf[i] = v;
        }
        __syncthreads();
        gemm<576, H, 1, true, true >(sm.xbuf,   succ_W1, succ_b1, sm.red, sm.hbufri, nullptr, 0);
        gemm<H,   H, 2, true, false>(sm.hbufri, succ_W2, succ_b2, sm.red, sm.succ,   nullptr, 0);

        // gate: sigmoid(gelu(RI[succ,prev] @ gW1 + b1) @ gW2 + b2)
        for (int i = t; i < BM * 384; i += TPB) {
            const int k = i >> 2, r = i & 3;
            sm.xbuf[i] = (k < H) ? sm.succ[r * H + k] : sm.prev[r * H + (k - H)];
        }
        __syncthreads();
        gemm<384, H, 1, true, false>(sm.xbuf, gate_W1, gate_b1, sm.red, sm.hbuf, nullptr, 0);
        {
            const int w = t >> 5, lane = t & 31;
            if (w < BM) {
                float v = 0.f;
#pragma unroll
                for (int i = 0; i < H / 32; i++) {
                    const int k = lane + 32 * i;
                    v = fmaf(sm.hbuf[w * H + k], __ldg(&gate_W2[k]), v);
                }
#pragma unroll
                for (int o = 16; o; o >>= 1) v += __shfl_xor_sync(0xffffffffu, v, o);
                v += gate_b2[0];
                const float gt = 1.f / (1.f + expf(-v));
                if (lane == 0) {
                    sm.gate[w] = gt;
                    out_gate[(b0 + w) * S_LEN + s] = gt;
                }
            }
        }
        __syncthreads();

        // hidden = gate*succ + (1-gate)*prev ; layernorm ; becomes prev (+RI into xbuf for dec)
        {
            const int w = t >> 5, lane = t & 31;
            if (w < BM) {
                const float g = sm.gate[w];
                float lv[H / 32];
                float mean = 0.f;
#pragma unroll
                for (int i = 0; i < H / 32; i++) {
                    const int h = lane + 32 * i;
                    float hv = g * sm.succ[w * H + h] + (1.f - g) * sm.prev[w * H + h];
                    lv[i] = hv; mean += hv;
                }
#pragma unroll
                for (int o = 16; o; o >>= 1) mean += __shfl_xor_sync(0xffffffffu, mean, o);
                mean *= (1.f / (float)H);
                float var = 0.f;
#pragma unroll
                for (int i = 0; i < H / 32; i++) { float d = lv[i] - mean; var = fmaf(d, d, var); }
#pragma unroll
                for (int o = 16; o; o >>= 1) var += __shfl_xor_sync(0xffffffffu, var, o);
                var *= (1.f / (float)H);
                const float rstd = rsqrtf(var + 1e-5f);
                float* oh = out_hidden + ((b0 + w) * S_LEN + s) * H;
#pragma unroll
                for (int i = 0; i < H / 32; i++) {
                    const int h = lane + 32 * i;
                    float o = (lv[i] - mean) * rstd * ln_g[h] + ln_b[h];
                    sm.prev[w * H + h] = o;
                    sm.xbuf[h * BM + w] = o;
                    oh[h] = o;
                }
            }
        }
        __syncthreads();

        // readout: logits = hidden @ dec_W
        gemm<H, VOC, 0, false, false>(sm.xbuf, dec_W, nullptr, sm.red, nullptr,
                                      out_logits + (b0 * S_LEN + s) * VOC, S_LEN * VOC);
    }
}

extern "C" void kernel_launch(void* const* d_in, const int* in_sizes, int n_in,
                              void* d_out, int out_size)
{
    const int*   ids          = (const int*)  d_in[0];
    const float* emb          = (const float*)d_in[1];
    const float* sel_W        = (const float*)d_in[2];
    const float* sel_b        = (const float*)d_in[3];
    const float* patch_values = (const float*)d_in[4];
    const float* bind_W1      = (const float*)d_in[5];
    const float* bind_b1      = (const float*)d_in[6];
    const float* bind_W2      = (const float*)d_in[7];
    const float* bind_b2      = (const float*)d_in[8];
    const float* phase_embed  = (const float*)d_in[9];
    const float* router_W     = (const float*)d_in[10];
    const float* router_b     = (const float*)d_in[11];
    const float* succ_W1      = (const float*)d_in[12];
    const float* succ_b1      = (const float*)d_in[13];
    const float* succ_W2      = (const float*)d_in[14];
    const float* succ_b2      = (const float*)d_in[15];
    const float* gate_W1      = (const float*)d_in[16];
    const float* gate_b1      = (const float*)d_in[17];
    const float* gate_W2      = (const float*)d_in[18];
    const float* gate_b2      = (const float*)d_in[19];
    const float* ln_g         = (const float*)d_in[20];
    const float* ln_b         = (const float*)d_in[21];
    const float* dec_W        = (const float*)d_in[22];

    spike_kernel<<<B_TOT / BM, TPB>>>(
        ids, emb, sel_W, sel_b, patch_values,
        bind_W1, bind_b1, bind_W2, bind_b2,
        phase_embed, router_W, router_b,
        succ_W1, succ_b1, succ_W2, succ_b2,
        gate_W1, gate_b1, gate_W2, gate_b2,
        ln_g, ln_b, dec_W, (float*)d_out);
}

// round 6
// speedup vs baseline: 1.2347x; 1.2347x over previous
#include <cuda_runtime.h>
#include <math.h>

#define TPB   768
#define BM    4
#define S_LEN 128
#define B_TOT 512
#define H     192
#define VOC   256
#define PP    64
#define PHH   16

// output buffer offsets (floats), concatenated in reference-return order
#define OFF_LOGITS 0
#define OFF_HIDDEN (512*128*256)
#define OFF_PW     (OFF_HIDDEN + 512*128*192)
#define OFF_PHW    (OFF_PW     + 512*128*64)
#define OFF_GATE   (OFF_PHW    + 512*128*16)

__device__ __forceinline__ float geluf(float x) {
    return 0.5f * x * (1.0f + erff(x * 0.7071067811865475f));
}

struct __align__(16) Smem {
    float red [12288];          // k-split partial scratch: NSEG*BM*N == 12288 for all shapes
    float xb_sel  [BM * 384];   // [tok | prev]
    float xb_bind [BM * 576];   // [tok | patch | prev]
    float xb_router[BM * 384];  // [sec | prev]
    float xb_succ [BM * 576];   // [sec | patch | phs]
    float xb_gate [BM * 384];   // [succ | prev]
    float xb_dec  [BM * H];     // hidden
    float hbuf [BM * H];        // bind1/succ1/gate1 intermediate
    float prev [BM * H];        // normal copy for LN
    float succ [BM * H];        // normal copy for LN
    float z64  [BM * PP];
    float z16  [BM * PHH];
};

// C[BM x N] = act( X[BM x K] @ W[K x N] + bias ), X normal row-major (row stride K).
// thread -> (col4 = t % (N/4), kseg = t / (N/4)); partials reduced through smem.
// ACT: 0 = none, 1 = gelu(exact), 2 = tanh
// Epilogue fan-out: up to two smem outputs (row strides rs1/rs2, col offsets off1/off2)
// plus optional global output outg with row stride g_rstride.
template<int K, int N, int ACT, bool HASB>
__device__ __forceinline__ void gemm(const float* __restrict__ xs,
                                     const float* __restrict__ W,
                                     const float* __restrict__ bias,
                                     float* __restrict__ red,
                                     float* __restrict__ o1, int rs1, int off1,
                                     float* __restrict__ o2, int rs2, int off2,
                                     float* __restrict__ outg, int g_rstride)
{
    constexpr int NC4  = N / 4;
    constexpr int NSEG = TPB / NC4;
    constexpr int KS   = K / NSEG;
    static_assert(NC4 * NSEG == TPB, "thread mapping must be exact");
    static_assert(KS * NSEG == K,    "k split must be exact");
    static_assert((NSEG % 4) == 0,   "epilogue 4-acc split must be exact");

    const int t   = threadIdx.x;
    const int c4  = t % NC4;
    const int seg = t / NC4;
    const float4* __restrict__ Wv = reinterpret_cast<const float4*>(W);

    float4 acc[BM];
#pragma unroll
    for (int r = 0; r < BM; r++) acc[r] = make_float4(0.f, 0.f, 0.f, 0.f);

    const int k0 = seg * KS;

    if constexpr ((KS % 4) == 0) {
        const float4* __restrict__ Xv = reinterpret_cast<const float4*>(xs);
#pragma unroll 2
        for (int kk4 = 0; kk4 < KS / 4; kk4++) {
            const int k = k0 + kk4 * 4;
            float4 xv[BM];
#pragma unroll
            for (int r = 0; r < BM; r++) xv[r] = Xv[(r * K + k) >> 2];
            float4 w0 = __ldg(&Wv[(k + 0) * NC4 + c4]);
            float4 w1 = __ldg(&Wv[(k + 1) * NC4 + c4]);
#pragma unroll
            for (int r = 0; r < BM; r++) {
                acc[r].x = fmaf(xv[r].x, w0.x, acc[r].x);
                acc[r].y = fmaf(xv[r].x, w0.y, acc[r].y);
                acc[r].z = fmaf(xv[r].x, w0.z, acc[r].z);
                acc[r].w = fmaf(xv[r].x, w0.w, acc[r].w);
                acc[r].x = fmaf(xv[r].y, w1.x, acc[r].x);
                acc[r].y = fmaf(xv[r].y, w1.y, acc[r].y);
                acc[r].z = fmaf(xv[r].y, w1.z, acc[r].z);
                acc[r].w = fmaf(xv[r].y, w1.w, acc[r].w);
            }
            float4 w2 = __ldg(&Wv[(k + 2) * NC4 + c4]);
            float4 w3 = __ldg(&Wv[(k + 3) * NC4 + c4]);
#pragma unroll
            for (int r = 0; r < BM; r++) {
                acc[r].x = fmaf(xv[r].z, w2.x, acc[r].x);
                acc[r].y = fmaf(xv[r].z, w2.y, acc[r].y);
                acc[r].z = fmaf(xv[r].z, w2.z, acc[r].z);
                acc[r].w = fmaf(xv[r].z, w2.w, acc[r].w);
                acc[r].x = fmaf(xv[r].w, w3.x, acc[r].x);
                acc[r].y = fmaf(xv[r].w, w3.y, acc[r].y);
                acc[r].z = fmaf(xv[r].w, w3.z, acc[r].z);
                acc[r].w = fmaf(xv[r].w, w3.w, acc[r].w);
            }
        }
    } else {
#pragma unroll
        for (int kk = 0; kk < KS; kk++) {
            const int k = k0 + kk;
            float4 w = __ldg(&Wv[k * NC4 + c4]);
#pragma unroll
            for (int r = 0; r < BM; r++) {
                float x = xs[r * K + k];
                acc[r].x = fmaf(x, w.x, acc[r].x);
                acc[r].y = fmaf(x, w.y, acc[r].y);
                acc[r].z = fmaf(x, w.z, acc[r].z);
                acc[r].w = fmaf(x, w.w, acc[r].w);
            }
        }
    }

    float4* redv = reinterpret_cast<float4*>(red);
#pragma unroll
    for (int r = 0; r < BM; r++) redv[(seg * BM + r) * NC4 + c4] = acc[r];
    __syncthreads();

    for (int i = t; i < BM * N; i += TPB) {
        const int r = i / N;
        const int n = i % N;
        float v0 = 0.f, v1 = 0.f, v2 = 0.f, v3 = 0.f;
#pragma unroll
        for (int g = 0; g < NSEG; g += 4) {
            v0 += red[((g + 0) * BM + r) * N + n];
            v1 += red[((g + 1) * BM + r) * N + n];
            v2 += red[((g + 2) * BM + r) * N + n];
            v3 += red[((g + 3) * BM + r) * N + n];
        }
        float v = (v0 + v1) + (v2 + v3);
        if (HASB) v += __ldg(&bias[n]);
        if (ACT == 1) v = geluf(v);
        if (ACT == 2) v = tanhf(v);
        if (o1) o1[r * rs1 + off1 + n] = v;
        if (o2) o2[r * rs2 + off2 + n] = v;
        if (outg) outg[r * g_rstride + n] = v;
    }
    __syncthreads();
}

// warp-per-row softmax over N (<= 64), in-place, mirrored to global
template<int N>
__device__ __forceinline__ void softmax_rows(float* __restrict__ z,
                                             float* __restrict__ outg, int g_rstride)
{
    const int w = threadIdx.x >> 5, lane = threadIdx.x & 31;
    if (w < BM) {
        float* row = z + w * N;
        constexpr int PER = (N + 31) / 32;
        float m = -3.0e38f;
#pragma unroll
        for (int i = 0; i < PER; i++) {
            int n = lane + 32 * i;
            if (n < N) m = fmaxf(m, row[n]);
        }
#pragma unroll
        for (int o = 16; o; o >>= 1) m = fmaxf(m, __shfl_xor_sync(0xffffffffu, m, o));
        float ev[PER];
        float sum = 0.f;
#pragma unroll
        for (int i = 0; i < PER; i++) {
            int n = lane + 32 * i;
            if (n < N) { ev[i] = expf(row[n] - m); sum += ev[i]; }
        }
#pragma unroll
        for (int o = 16; o; o >>= 1) sum += __shfl_xor_sync(0xffffffffu, sum, o);
        const float inv = 1.f / sum;
#pragma unroll
        for (int i = 0; i < PER; i++) {
            int n = lane + 32 * i;
            if (n < N) {
                float v = ev[i] * inv;
                row[n] = v;
                outg[w * g_rstride + n] = v;
            }
        }
    }
}

__global__ void __launch_bounds__(TPB, 1)
spike_kernel(const int* __restrict__ ids_g,      const float* __restrict__ emb,
             const float* __restrict__ sel_W,    const float* __restrict__ sel_b,
             const float* __restrict__ patch_values,
             const float* __restrict__ bind_W1,  const float* __restrict__ bind_b1,
             const float* __restrict__ bind_W2,  const float* __restrict__ bind_b2,
             const float* __restrict__ phase_embed,
             const float* __restrict__ router_W, const float* __restrict__ router_b,
             const float* __restrict__ succ_W1,  const float* __restrict__ succ_b1,
             const float* __restrict__ succ_W2,  const float* __restrict__ succ_b2,
             const float* __restrict__ gate_W1,  const float* __restrict__ gate_b1,
             const float* __restrict__ gate_W2,  const float* __restrict__ gate_b2,
             const float* __restrict__ ln_g,     const float* __restrict__ ln_b,
             const float* __restrict__ dec_W,
             float* __restrict__ out)
{
    __shared__ Smem sm;
    const int t  = threadIdx.x;
    const int b0 = blockIdx.x * BM;

    float* out_logits = out + OFF_LOGITS;
    float* out_hidden = out + OFF_HIDDEN;
    float* out_pw     = out + OFF_PW;
    float* out_phw    = out + OFF_PHW;
    float* out_gate   = out + OFF_GATE;

    // zero prev (normal copy) and all prev-slots of concat buffers
    for (int i = t; i < BM * H; i += TPB) {
        const int r = i / H, h = i % H;
        sm.prev[i] = 0.f;
        sm.xb_sel   [r * 384 + H     + h] = 0.f;
        sm.xb_bind  [r * 576 + 2 * H + h] = 0.f;
        sm.xb_router[r * 384 + H     + h] = 0.f;
        sm.xb_gate  [r * 384 + H     + h] = 0.f;
    }
    __syncthreads();

    for (int s = 0; s < S_LEN; s++) {
        // tok gather -> tok slots of xb_sel and xb_bind (1 elem/thread)
        {
            const int r = t / H, h = t % H;   // TPB == BM*H
            const int id = __ldg(&ids_g[(b0 + r) * S_LEN + s]);
            const float v = __ldg(&emb[id * H + h]);
            sm.xb_sel [r * 384 + h] = v;
            sm.xb_bind[r * 576 + h] = v;
        }
        __syncthreads();

        // patch selector: softmax([tok,prev] @ sel_W + b) @ patch_values
        gemm<384, PP, 0, true>(sm.xb_sel, sel_W, sel_b, sm.red,
                               sm.z64, PP, 0, nullptr, 0, 0, nullptr, 0);
        softmax_rows<PP>(sm.z64, out_pw + (b0 * S_LEN + s) * PP, S_LEN * PP);
        __syncthreads();
        gemm<PP, H, 0, false>(sm.z64, patch_values, nullptr, sm.red,
                              sm.xb_bind, 576, H, sm.xb_succ, 576, H, nullptr, 0);

        // section binder: tanh(gelu([tok,patch,prev] @ W1 + b1) @ W2 + b2) -> sec
        gemm<576, H, 1, true>(sm.xb_bind, bind_W1, bind_b1, sm.red,
                              sm.hbuf, H, 0, nullptr, 0, 0, nullptr, 0);
        gemm<H,   H, 2, true>(sm.hbuf, bind_W2, bind_b2, sm.red,
                              sm.xb_router, 384, 0, sm.xb_succ, 576, 0, nullptr, 0);

        // phase routing: softmax([sec,prev] @ router_W + b) @ phase_embed -> phs
        gemm<384, PHH, 0, true>(sm.xb_router, router_W, router_b, sm.red,
                                sm.z16, PHH, 0, nullptr, 0, 0, nullptr, 0);
        softmax_rows<PHH>(sm.z16, out_phw + (b0 * S_LEN + s) * PHH, S_LEN * PHH);
        __syncthreads();
        gemm<PHH, H, 0, false>(sm.z16, phase_embed, nullptr, sm.red,
                               sm.xb_succ, 576, 2 * H, nullptr, 0, 0, nullptr, 0);

        // successor: tanh(gelu([sec,patch,phs] @ W1 + b1) @ W2 + b2) -> succ
        gemm<576, H, 1, true>(sm.xb_succ, succ_W1, succ_b1, sm.red,
                              sm.hbuf, H, 0, nullptr, 0, 0, nullptr, 0);
        gemm<H,   H, 2, true>(sm.hbuf, succ_W2, succ_b2, sm.red,
                              sm.xb_gate, 384, 0, sm.succ, H, 0, nullptr, 0);

        // gate hidden layer: gelu([succ,prev] @ gW1 + b1)
        gemm<384, H, 1, true>(sm.xb_gate, gate_W1, gate_b1, sm.red,
                              sm.hbuf, H, 0, nullptr, 0, 0, nullptr, 0);

        // fused: gate2 dot + sigmoid + hidden mix + layernorm + fan-out (4 warps)
        {
            const int w = t >> 5, lane = t & 31;
            if (w < BM) {
                float v = 0.f;
#pragma unroll
                for (int i = 0; i < H / 32; i++) {
                    const int k = lane + 32 * i;
                    v = fmaf(sm.hbuf[w * H + k], __ldg(&gate_W2[k]), v);
                }
#pragma unroll
                for (int o = 16; o; o >>= 1) v += __shfl_xor_sync(0xffffffffu, v, o);
                v += gate_b2[0];
                const float g = 1.f / (1.f + expf(-v));
                if (lane == 0) out_gate[(b0 + w) * S_LEN + s] = g;

                float lv[H / 32];
                float mean = 0.f;
#pragma unroll
                for (int i = 0; i < H / 32; i++) {
                    const int h = lane + 32 * i;
                    float hv = g * sm.succ[w * H + h] + (1.f - g) * sm.prev[w * H + h];
                    lv[i] = hv; mean += hv;
                }
#pragma unroll
                for (int o = 16; o; o >>= 1) mean += __shfl_xor_sync(0xffffffffu, mean, o);
                mean *= (1.f / (float)H);
                float var = 0.f;
#pragma unroll
                for (int i = 0; i < H / 32; i++) { float d = lv[i] - mean; var = fmaf(d, d, var); }
#pragma unroll
                for (int o = 16; o; o >>= 1) var += __shfl_xor_sync(0xffffffffu, var, o);
                var *= (1.f / (float)H);
                const float rstd = rsqrtf(var + 1e-5f);
                float* oh = out_hidden + ((b0 + w) * S_LEN + s) * H;
#pragma unroll
                for (int i = 0; i < H / 32; i++) {
                    const int h = lane + 32 * i;
                    float o = (lv[i] - mean) * rstd * __ldg(&ln_g[h]) + __ldg(&ln_b[h]);
                    sm.prev[w * H + h] = o;
                    sm.xb_dec[w * H + h] = o;
                    sm.xb_sel   [w * 384 + H     + h] = o;
                    sm.xb_bind  [w * 576 + 2 * H + h] = o;
                    sm.xb_router[w * 384 + H     + h] = o;
                    sm.xb_gate  [w * 384 + H     + h] = o;
                    oh[h] = o;
                }
            }
        }
        __syncthreads();

        // readout: logits = hidden @ dec_W
        gemm<H, VOC, 0, false>(sm.xb_dec, dec_W, nullptr, sm.red,
                               nullptr, 0, 0, nullptr, 0, 0,
                               out_logits + (b0 * S_LEN + s) * VOC, S_LEN * VOC);
    }
}

extern "C" void kernel_launch(void* const* d_in, const int* in_sizes, int n_in,
                              void* d_out, int out_size)
{
    const int*   ids          = (const int*)  d_in[0];
    const float* emb          = (const float*)d_in[1];
    const float* sel_W        = (const float*)d_in[2];
    const float* sel_b        = (const float*)d_in[3];
    const float* patch_values = (const float*)d_in[4];
    const float* bind_W1      = (const float*)d_in[5];
    const float* bind_b1      = (const float*)d_in[6];
    const float* bind_W2      = (const float*)d_in[7];
    const float* bind_b2      = (const float*)d_in[8];
    const float* phase_embed  = (const float*)d_in[9];
    const float* router_W     = (const float*)d_in[10];
    const float* router_b     = (const float*)d_in[11];
    const float* succ_W1      = (const float*)d_in[12];
    const float* succ_b1      = (const float*)d_in[13];
    const float* succ_W2      = (const float*)d_in[14];
    const float* succ_b2      = (const float*)d_in[15];
    const float* gate_W1      = (const float*)d_in[16];
    const float* gate_b1      = (const float*)d_in[17];
    const float* gate_W2      = (const float*)d_in[18];
    const float* gate_b2      = (const float*)d_in[19];
    const float* ln_g         = (const float*)d_in[20];
    const float* ln_b         = (const float*)d_in[21];
    const float* dec_W        = (const float*)d_in[22];

    spike_kernel<<<B_TOT / BM, TPB>>>(
        ids, emb, sel_W, sel_b, patch_values,
        bind_W1, bind_b1, bind_W2, bind_b2,
        phase_embed, router_W, router_b,
        succ_W1, succ_b1, succ_W2, succ_b2,
        gate_W1, gate_b1, gate_W2, gate_b2,
        ln_g, ln_b, dec_W, (float*)d_out);
}